// round 16
// baseline (speedup 1.0000x reference)
#include <cuda_runtime.h>
#include <cuda_bf16.h>
#include <math.h>
#include <stdint.h>

#define BB 4
#define NN 384
#define DD 64
#define NTH 256
#define NNODE (BB * NN)

// smem kk layout (32 k16-steps):
// kk0-3  W1a' (per-node: W1a + diag(ht) W1c)   [G1 hs]
// kk4-7  W1b                                   [G1 |hs-ht|]
// kk8-11 W1d                                   [G1 e]
// kk12-15 W2                                   [G2]
// kk16-23 Wg (e, de)                           [G3]
// kk24-31 Wm (hs rows 0-63, e_new rows 128-191)[G4]
#define KK_SM 32
#define NFRAG 8
__device__ uint4 g_Wf[KK_SM * NFRAG * 32];
__device__ uint4 g_Wc[4 * NFRAG * 32];
__device__ uint4 g_W1f[NNODE * 4 * NFRAG * 32];
__device__ float d_b1p[NNODE * DD];
__device__ float d_bmp[NNODE * DD];
__device__ float d_agg[NNODE * DD];

#define SWF_U4   (KK_SM * NFRAG * 32)               // 8192 uint4 = 32768 u32
#define OFF_B1P  (SWF_U4 * 4)                       // 32768
#define OFF_B2   (OFF_B1P + 64)
#define OFF_BG   (OFF_B2 + 64)
#define OFF_BMP  (OFF_BG + 64)
#define OFF_SHI  (OFF_BMP + 64)
#define OFF_RED  (OFF_SHI + 64)
#define OFF_EPF  (OFF_RED + 512)                    // float2-aligned
#define EPF_WORDS (2 * 16 * NTH * 2)
#define SMEM_U32 (OFF_EPF + EPF_WORDS)
#define SMEM_BYTES (SMEM_U32 * 4)

// sigmoid via hardware tanh: 1 MUFU + 1 FMA
__device__ __forceinline__ float fsig(float x) {
    float th;
    asm("tanh.approx.f32 %0, %1;" : "=f"(th) : "f"(0.5f * x));
    return fmaf(0.5f, th, 0.5f);
}
// silu(x) = 0.5x + 0.5x*tanh(x/2) : mul + MUFU + fma
__device__ __forceinline__ float fsilu(float x) {
    float hx = 0.5f * x;
    float th;
    asm("tanh.approx.f32 %0, %1;" : "=f"(th) : "f"(hx));
    return fmaf(hx, th, hx);
}

__device__ __forceinline__ uint32_t smem_u32(const void *p) {
    uint32_t a;
    asm("{ .reg .u64 t; cvta.to.shared.u64 t, %1; cvt.u32.u64 %0, t; }" : "=r"(a) : "l"(p));
    return a;
}

// fast split: hi = bf16x2(v1,v0) via single packed cvt; lo = bf16x2(residuals)
__device__ __forceinline__ void splitpk(float v0, float v1, unsigned &whi, unsigned &wlo) {
    unsigned ph;
    asm("cvt.rn.bf16x2.f32 %0, %1, %2;" : "=r"(ph) : "f"(v1), "f"(v0));
    float f0 = __uint_as_float(ph << 16);
    float f1 = __uint_as_float(ph & 0xffff0000u);
    asm("cvt.rn.bf16x2.f32 %0, %1, %2;" : "=r"(wlo) : "f"(v1 - f1), "f"(v0 - f0));
    whi = ph;
}
__device__ __forceinline__ void up2(unsigned w, float &f0, float &f1) {
    f0 = __uint_as_float(w << 16);
    f1 = __uint_as_float(w & 0xffff0000u);
}
// reconstruct float2 from hi+lo frag words
__device__ __forceinline__ float2 rec2(unsigned wh, unsigned wl) {
    float h0, h1, l0, l1;
    up2(wh, h0, h1);
    up2(wl, l0, l1);
    return make_float2(h0 + l0, h1 + l1);
}

__device__ __forceinline__ void mma4(float *d, const unsigned *a, unsigned b0, unsigned b1) {
    asm("mma.sync.aligned.m16n8k16.row.col.f32.bf16.bf16.f32 "
        "{%0,%1,%2,%3}, {%4,%5,%6,%7}, {%8,%9}, {%0,%1,%2,%3};"
        : "+f"(d[0]), "+f"(d[1]), "+f"(d[2]), "+f"(d[3])
        : "r"(a[0]), "r"(a[1]), "r"(a[2]), "r"(a[3]), "r"(b0), "r"(b1));
}

// One k16-step: 2 groups of 4 fragments. Per group: 4x LDS.128 (whole {bh,bl}),
// then 3 passes of 4 independent MMAs from held registers.
__device__ __forceinline__ void gemm_kk(float (&D)[8][4], const unsigned *ah, const unsigned *al,
                                        const uint4 *__restrict__ Wp)
{
#pragma unroll
    for (int grp = 0; grp < 2; grp++) {
        uint4 bq[4];
#pragma unroll
        for (int q = 0; q < 4; q++) bq[q] = Wp[(grp * 4 + q) * 32];
#pragma unroll
        for (int q = 0; q < 4; q++) mma4(D[grp * 4 + q], ah, bq[q].x, bq[q].y);
#pragma unroll
        for (int q = 0; q < 4; q++) mma4(D[grp * 4 + q], ah, bq[q].z, bq[q].w);
#pragma unroll
        for (int q = 0; q < 4; q++) mma4(D[grp * 4 + q], al, bq[q].x, bq[q].y);
    }
}

__device__ __forceinline__ void cp_async8(uint32_t saddr, const void *gaddr) {
    asm volatile("cp.async.ca.shared.global [%0], [%1], 8;" :: "r"(saddr), "l"(gaddr) : "memory");
}

// ---- prep: pack weight B-fragments (hi/lo bf16) ----
__global__ void prep_kernel(const float *__restrict__ W1, const float *__restrict__ W2,
                            const float *__restrict__ Wg, const float *__restrict__ Wm)
{
    const int kk = blockIdx.x;          // 0..35 (32-35 = W1c -> g_Wc)
    const int tid = threadIdx.x;
    const int f = tid >> 5;
    const int lane = tid & 31;
    const int t = lane & 3;
    const int n = 8 * f + (lane >> 2);

    const float *W; int kb;
    if (kk < 8)       { W = W1; kb = kk * 16; }
    else if (kk < 12) { W = W1; kb = 192 + (kk - 8) * 16; }
    else if (kk < 16) { W = W2; kb = (kk - 12) * 16; }
    else if (kk < 24) { W = Wg; kb = (kk - 16) * 16; }
    else if (kk < 28) { W = Wm; kb = (kk - 24) * 16; }
    else if (kk < 32) { W = Wm; kb = 128 + (kk - 28) * 16; }
    else              { W = W1; kb = 128 + (kk - 32) * 16; }

    float w0 = W[(kb + 2 * t) * 64 + n];
    float w1 = W[(kb + 2 * t + 1) * 64 + n];
    float w2 = W[(kb + 2 * t + 8) * 64 + n];
    float w3 = W[(kb + 2 * t + 9) * 64 + n];
    unsigned h0, l0, h1, l1;
    splitpk(w0, w1, h0, l0);
    splitpk(w2, w3, h1, l1);
    if (kk < 32) g_Wf[(kk * NFRAG + f) * 32 + lane] = make_uint4(h0, h1, l0, l1);
    else         g_Wc[((kk - 32) * NFRAG + f) * 32 + lane] = make_uint4(h0, h1, l0, l1);
}

// ---- fold W1a' = W1a + diag(ht)*W1c per node ----
__global__ void fold_w1a_kernel(const float *__restrict__ h)
{
    const int gid = blockIdx.x * 256 + threadIdx.x;
    const int node = gid >> 10;
    const int idx = gid & 1023;
    const int kk_ = idx >> 8;
    const int t_ = idx & 3;
    const int kl = kk_ * 16 + 2 * t_;
    const float *hp = &h[node * DD];

    uint4 va = g_Wf[idx];
    uint4 vc = g_Wc[idx];
    float a0, a1, a2, a3, x0, x1, x2, x3;
    float c0, c1, c2, c3, y0, y1, y2, y3;
    up2(va.x, a0, a1); up2(va.z, x0, x1); a0 += x0; a1 += x1;
    up2(va.y, a2, a3); up2(va.w, x2, x3); a2 += x2; a3 += x3;
    up2(vc.x, c0, c1); up2(vc.z, y0, y1); c0 += y0; c1 += y1;
    up2(vc.y, c2, c3); up2(vc.w, y2, y3); c2 += y2; c3 += y3;
    unsigned nh0, nl0, nh1, nl1;
    splitpk(fmaf(hp[kl], c0, a0), fmaf(hp[kl + 1], c1, a1), nh0, nl0);
    splitpk(fmaf(hp[kl + 8], c2, a2), fmaf(hp[kl + 9], c3, a3), nh1, nl1);
    g_W1f[node * 1024 + idx] = make_uint4(nh0, nh1, nl0, nl1);
}

// ---- fold biases per node ----
__global__ void fold_bias_kernel(const float *__restrict__ h,
                                 const float *__restrict__ W1, const float *__restrict__ b1,
                                 const float *__restrict__ Wm, const float *__restrict__ bm)
{
    __shared__ float sh[64];
    const int node = blockIdx.x;
    const int c = threadIdx.x;
    sh[c] = h[node * DD + c];
    __syncthreads();
    float a = b1[c], m = bm[c];
#pragma unroll 8
    for (int k = 0; k < 64; k++) {
        a = fmaf(sh[k], W1[k * 64 + c], a);
        m = fmaf(sh[k], Wm[(64 + k) * 64 + c], m);
    }
    d_b1p[node * DD + c] = a;
    d_bmp[node * DD + c] = m;
}

__global__ void __launch_bounds__(NTH, 1) edge_kernel(
    const float *__restrict__ h, const float *__restrict__ e,
    const float *__restrict__ b2, const float *__restrict__ bg,
    float *__restrict__ e_out)
{
    extern __shared__ unsigned smu[];
    uint4 *sWfm = (uint4 *)smu;
    const uint4 *sW4 = (const uint4 *)smu;
    float *sb1p = (float *)(smu + OFF_B1P);
    float *sb2 = (float *)(smu + OFF_B2);
    float *sbg = (float *)(smu + OFF_BG);
    float *sbmp = (float *)(smu + OFF_BMP);
    float *shi = (float *)(smu + OFF_SHI);
    float *sred = (float *)(smu + OFF_RED);

    const int tid = threadIdx.x;
    const int w = tid >> 5;
    const int lane = tid & 31;
    const int g = lane >> 2;
    const int t = lane & 3;

    const int blk = blockIdx.x;
    const int b = blk / NN;
    const int i = blk - b * NN;
    const size_t erow = ((size_t)(b * NN + i)) * NN;
    const int node = b * NN + i;

    const uint32_t epfBase = smem_u32(smu + OFF_EPF);
    const float2 *epfRd = (const float2 *)(smu + OFF_EPF);

    // ---- stage weights (kk0-3 per-node) + biases + h_i ----
    {
        const uint4 *wsrc = &g_W1f[node * 1024];
        for (int idx = tid; idx < SWF_U4; idx += NTH)
            sWfm[idx] = (idx < 1024) ? wsrc[idx] : g_Wf[idx];
    }
    if (tid < 64) {
        sb1p[tid] = d_b1p[node * DD + tid];
        sbmp[tid] = d_bmp[node * DD + tid];
        sb2[tid] = b2[tid];
        sbg[tid] = bg[tid];
        shi[tid] = h[node * DD + tid];
    }
    __syncthreads();

    float2 aggc[8];
#pragma unroll
    for (int f = 0; f < 8; f++) aggc[f] = make_float2(0.f, 0.f);

    for (int j0 = 0; j0 < NN; j0 += 128) {
        const int rA = j0 + 16 * w + g;
        const int rB = rA + 8;
        const float *hA = &h[(b * NN + rA) * DD];
        const float *hB = &h[(b * NN + rB) * DD];

        // ---- prefetch next tile's e (per-thread slots; no barrier needed) ----
        const int nb = (j0 >> 7) & 1;
        const bool havePf = (j0 + 128 < NN);
        if (havePf) {
            const float *enA = &e[(erow + rA + 128) * DD];
            const float *enB = &e[(erow + rB + 128) * DD];
#pragma unroll
            for (int m = 0; m < 4; m++)
#pragma unroll
                for (int p = 0; p < 2; p++) {
                    const int c = 16 * m + 8 * p + 2 * t;
                    const int q = m * 4 + p * 2;
                    cp_async8(epfBase + nb * (16 * NTH * 8) + q * (NTH * 8) + tid * 8, &enA[c]);
                    cp_async8(epfBase + nb * (16 * NTH * 8) + (q + 1) * (NTH * 8) + tid * 8, &enB[c]);
                }
            asm volatile("cp.async.commit_group;" ::: "memory");
        }

        // ---- load hs + e; split ONCE into canonical frags ----
        unsigned hsFh[4][4], hsFl[4][4], eFh[4][4], eFl[4][4];
#pragma unroll
        for (int m = 0; m < 4; m++)
#pragma unroll
            for (int p = 0; p < 2; p++) {
                const int c = 16 * m + 8 * p + 2 * t;
                float2 a = *(const float2 *)&hA[c];
                float2 bv = *(const float2 *)&hB[c];
                splitpk(a.x, a.y, hsFh[m][2 * p], hsFl[m][2 * p]);
                splitpk(bv.x, bv.y, hsFh[m][2 * p + 1], hsFl[m][2 * p + 1]);
            }
        if (j0 == 0) {
            const float *epA = &e[(erow + rA) * DD];
            const float *epB = &e[(erow + rB) * DD];
#pragma unroll
            for (int m = 0; m < 4; m++)
#pragma unroll
                for (int p = 0; p < 2; p++) {
                    const int c = 16 * m + 8 * p + 2 * t;
                    float2 ev = *(const float2 *)&epA[c];
                    float2 ew = *(const float2 *)&epB[c];
                    splitpk(ev.x, ev.y, eFh[m][2 * p], eFl[m][2 * p]);
                    splitpk(ew.x, ew.y, eFh[m][2 * p + 1], eFl[m][2 * p + 1]);
                }
        } else {
            if (havePf) asm volatile("cp.async.wait_group 1;" ::: "memory");
            else        asm volatile("cp.async.wait_group 0;" ::: "memory");
            const int pb = ((j0 >> 7) + 1) & 1;   // buffer written last tile
            const float2 *pf = epfRd + pb * (16 * NTH) + tid;
#pragma unroll
            for (int m = 0; m < 4; m++)
#pragma unroll
                for (int p = 0; p < 2; p++) {
                    const int q = m * 4 + p * 2;
                    float2 ev = pf[q * NTH];
                    float2 ew = pf[(q + 1) * NTH];
                    splitpk(ev.x, ev.y, eFh[m][2 * p], eFl[m][2 * p]);
                    splitpk(ew.x, ew.y, eFh[m][2 * p + 1], eFl[m][2 * p + 1]);
                }
        }

        // ---- G1: D = hs@W1a' + |hs-ht|@W1b + e@W1d  (12 k-steps) ----
        float D[8][4];
#pragma unroll
        for (int f = 0; f < 8; f++) { D[f][0] = D[f][1] = D[f][2] = D[f][3] = 0.f; }
#pragma unroll
        for (int m = 0; m < 4; m++)
            gemm_kk(D, hsFh[m], hsFl[m], sW4 + (m * 8) * 32 + lane);
#pragma unroll
        for (int m = 0; m < 4; m++) {
            // |hs - ht| rebuilt from frags; ht from smem
            unsigned dh_[4], dl_[4];
#pragma unroll
            for (int p = 0; p < 2; p++) {
                const int c = 16 * m + 8 * p + 2 * t;
                float2 ht2 = *(const float2 *)&shi[c];
                float2 va = rec2(hsFh[m][2 * p], hsFl[m][2 * p]);
                float2 vb = rec2(hsFh[m][2 * p + 1], hsFl[m][2 * p + 1]);
                splitpk(fabsf(va.x - ht2.x), fabsf(va.y - ht2.y), dh_[2 * p], dl_[2 * p]);
                splitpk(fabsf(vb.x - ht2.x), fabsf(vb.y - ht2.y), dh_[2 * p + 1], dl_[2 * p + 1]);
            }
            gemm_kk(D, dh_, dl_, sW4 + ((4 + m) * 8) * 32 + lane);
        }
#pragma unroll
        for (int m = 0; m < 4; m++)
            gemm_kk(D, eFh[m], eFl[m], sW4 + ((8 + m) * 8) * 32 + lane);

        // ---- t1 = silu(D + b1') as A-frags ----
        unsigned t1h[4][4], t1l[4][4];
#pragma unroll
        for (int m = 0; m < 4; m++) {
            const int f0 = 2 * m, f1 = 2 * m + 1;
            float2 bb0 = *(const float2 *)&sb1p[8 * f0 + 2 * t];
            float2 bb1 = *(const float2 *)&sb1p[8 * f1 + 2 * t];
            splitpk(fsilu(D[f0][0] + bb0.x), fsilu(D[f0][1] + bb0.y), t1h[m][0], t1l[m][0]);
            splitpk(fsilu(D[f0][2] + bb0.x), fsilu(D[f0][3] + bb0.y), t1h[m][1], t1l[m][1]);
            splitpk(fsilu(D[f1][0] + bb1.x), fsilu(D[f1][1] + bb1.y), t1h[m][2], t1l[m][2]);
            splitpk(fsilu(D[f1][2] + bb1.x), fsilu(D[f1][3] + bb1.y), t1h[m][3], t1l[m][3]);
        }

        // ---- G2: D2 = t1 @ W2 (+b2 in place) ----
        float D2[8][4];
#pragma unroll
        for (int f = 0; f < 8; f++) { D2[f][0] = D2[f][1] = D2[f][2] = D2[f][3] = 0.f; }
#pragma unroll
        for (int kk = 0; kk < 4; kk++)
            gemm_kk(D2, t1h[kk], t1l[kk], sW4 + ((12 + kk) * 8) * 32 + lane);
#pragma unroll
        for (int f = 0; f < 8; f++) {
            float2 bb = *(const float2 *)&sb2[8 * f + 2 * t];
            D2[f][0] += bb.x; D2[f][1] += bb.y; D2[f][2] += bb.x; D2[f][3] += bb.y;
        }

        // ---- G3: D3 = [e, de] @ Wg  (e from canonical frags) ----
        float D3[8][4];
#pragma unroll
        for (int f = 0; f < 8; f++) { D3[f][0] = D3[f][1] = D3[f][2] = D3[f][3] = 0.f; }
#pragma unroll
        for (int kk = 0; kk < 4; kk++)
            gemm_kk(D3, eFh[kk], eFl[kk], sW4 + ((16 + kk) * 8) * 32 + lane);
#pragma unroll
        for (int kk = 0; kk < 4; kk++) {     // de block (from D2 regs)
            unsigned ah[4], al[4];
            splitpk(D2[2 * kk][0], D2[2 * kk][1], ah[0], al[0]);
            splitpk(D2[2 * kk][2], D2[2 * kk][3], ah[1], al[1]);
            splitpk(D2[2 * kk + 1][0], D2[2 * kk + 1][1], ah[2], al[2]);
            splitpk(D2[2 * kk + 1][2], D2[2 * kk + 1][3], ah[3], al[3]);
            gemm_kk(D3, ah, al, sW4 + ((20 + kk) * 8) * 32 + lane);
        }

        // ---- e_new = de + g*(e - de); store; refill eF with e_new frags ----
        float *eoA = &e_out[(erow + rA) * DD];
        float *eoB = &e_out[(erow + rB) * DD];
#pragma unroll
        for (int m = 0; m < 4; m++)
#pragma unroll
            for (int p = 0; p < 2; p++) {
                const int f = 2 * m + p;
                float2 bb = *(const float2 *)&sbg[8 * f + 2 * t];
                float2 ea = rec2(eFh[m][2 * p], eFl[m][2 * p]);
                float2 eb = rec2(eFh[m][2 * p + 1], eFl[m][2 * p + 1]);
                float g0 = fsig(D3[f][0] + bb.x), g1 = fsig(D3[f][1] + bb.y);
                float g2 = fsig(D3[f][2] + bb.x), g3 = fsig(D3[f][3] + bb.y);
                float2 nA, nB;
                nA.x = fmaf(g0, ea.x - D2[f][0], D2[f][0]);
                nA.y = fmaf(g1, ea.y - D2[f][1], D2[f][1]);
                nB.x = fmaf(g2, eb.x - D2[f][2], D2[f][2]);
                nB.y = fmaf(g3, eb.y - D2[f][3], D2[f][3]);
                const int c = 16 * m + 8 * p + 2 * t;
                *(float2 *)&eoA[c] = nA;
                *(float2 *)&eoB[c] = nB;
                splitpk(nA.x, nA.y, eFh[m][2 * p], eFl[m][2 * p]);
                splitpk(nB.x, nB.y, eFh[m][2 * p + 1], eFl[m][2 * p + 1]);
            }

        // ---- G4: D4 = [hs, e_new] @ Wm'  (both from canonical frags) ----
        float D4[8][4];
#pragma unroll
        for (int f = 0; f < 8; f++) { D4[f][0] = D4[f][1] = D4[f][2] = D4[f][3] = 0.f; }
#pragma unroll
        for (int kk = 0; kk < 4; kk++)
            gemm_kk(D4, hsFh[kk], hsFl[kk], sW4 + ((24 + kk) * 8) * 32 + lane);
#pragma unroll
        for (int kk = 0; kk < 4; kk++)
            gemm_kk(D4, eFh[kk], eFl[kk], sW4 + ((28 + kk) * 8) * 32 + lane);

        // ---- msg = silu(D4 + bm'), diagonal mask, column-accumulate ----
        const bool mA = (rA != i), mB = (rB != i);
#pragma unroll
        for (int f = 0; f < 8; f++) {
            float2 bb = *(const float2 *)&sbmp[8 * f + 2 * t];
            float m0 = fsilu(D4[f][0] + bb.x), m1 = fsilu(D4[f][1] + bb.y);
            float m2 = fsilu(D4[f][2] + bb.x), m3 = fsilu(D4[f][3] + bb.y);
            aggc[f].x += (mA ? m0 : 0.f) + (mB ? m2 : 0.f);
            aggc[f].y += (mA ? m1 : 0.f) + (mB ? m3 : 0.f);
        }
    }

    // ---- agg reduce: over g lanes (shfl), then over warps (smem) ----
#pragma unroll
    for (int f = 0; f < 8; f++) {
        float x = aggc[f].x, y = aggc[f].y;
        x += __shfl_xor_sync(0xffffffffu, x, 4);
        x += __shfl_xor_sync(0xffffffffu, x, 8);
        x += __shfl_xor_sync(0xffffffffu, x, 16);
        y += __shfl_xor_sync(0xffffffffu, y, 4);
        y += __shfl_xor_sync(0xffffffffu, y, 8);
        y += __shfl_xor_sync(0xffffffffu, y, 16);
        aggc[f].x = x; aggc[f].y = y;
    }
    if (lane < 4) {
#pragma unroll
        for (int f = 0; f < 8; f++) {
            sred[w * 64 + 8 * f + 2 * lane] = aggc[f].x;
            sred[w * 64 + 8 * f + 2 * lane + 1] = aggc[f].y;
        }
    }
    __syncthreads();
    if (tid < 64) {
        float s = 0.f;
#pragma unroll
        for (int ww = 0; ww < 8; ww++) s += sred[ww * 64 + tid];
        d_agg[node * DD + tid] = s * (1.0f / (NN - 1));
    }
}

__global__ void __launch_bounds__(64) node_kernel(
    const float *__restrict__ h,
    const float *__restrict__ Wu, const float *__restrict__ bu,
    const float *__restrict__ Wg, const float *__restrict__ bg,
    float *__restrict__ h_out)
{
    __shared__ float xs[128];
    __shared__ float dhs[64];
    const int node = blockIdx.x;
    const int c = threadIdx.x;

    xs[c] = h[node * 64 + c];
    xs[64 + c] = d_agg[node * 64 + c];
    __syncthreads();

    float acc = bu[c];
#pragma unroll 8
    for (int k = 0; k < 128; k++) acc = fmaf(xs[k], Wu[k * 64 + c], acc);
    float dh = fsilu(acc);
    dhs[c] = dh;
    __syncthreads();

    float a2 = bg[c];
#pragma unroll 8
    for (int k = 0; k < 64; k++) a2 = fmaf(xs[k], Wg[k * 64 + c], a2);
#pragma unroll 8
    for (int k = 0; k < 64; k++) a2 = fmaf(dhs[k], Wg[(64 + k) * 64 + c], a2);
    float gg = fsig(a2);
    h_out[node * 64 + c] = gg * xs[c] + (1.0f - gg) * dh;
}

extern "C" void kernel_launch(void* const* d_in, const int* in_sizes, int n_in,
                              void* d_out, int out_size)
{
    const float* h   = (const float*)d_in[0];
    const float* e   = (const float*)d_in[1];
    const float* W1  = (const float*)d_in[2];
    const float* b1  = (const float*)d_in[3];
    const float* W2  = (const float*)d_in[4];
    const float* b2  = (const float*)d_in[5];
    const float* Weg = (const float*)d_in[6];
    const float* beg = (const float*)d_in[7];
    const float* Wm  = (const float*)d_in[8];
    const float* bm  = (const float*)d_in[9];
    const float* Wu  = (const float*)d_in[10];
    const float* bu  = (const float*)d_in[11];
    const float* Wga = (const float*)d_in[12];
    const float* bga = (const float*)d_in[13];

    float* out = (float*)d_out;
    float* h_out = out;                       // (B,N,D)
    float* e_out = out + BB * NN * DD;        // (B,N,N,D)

    cudaFuncSetAttribute(edge_kernel, cudaFuncAttributeMaxDynamicSharedMemorySize, SMEM_BYTES);

    prep_kernel<<<36, 256>>>(W1, W2, Weg, Wm);
    fold_w1a_kernel<<<NNODE * 1024 / 256, 256>>>(h);
    fold_bias_kernel<<<NNODE, 64>>>(h, W1, b1, Wm, bm);
    edge_kernel<<<NNODE, NTH, SMEM_BYTES>>>(h, e, b2, beg, e_out);
    node_kernel<<<NNODE, 64>>>(h, Wu, bu, Wga, bga, h_out);
}

// round 17
// speedup vs baseline: 1.1508x; 1.1508x over previous
#include <cuda_runtime.h>
#include <cuda_bf16.h>
#include <math.h>
#include <stdint.h>

#define BB 4
#define NN 384
#define DD 64
#define NTH 256
#define NNODE (BB * NN)

// smem kk layout (32 k16-steps):
// kk0-3  W1a' (per-node: W1a + diag(ht) W1c)   [G1 hs]
// kk4-7  W1b                                   [G1 |hs-ht|]
// kk8-11 W1d                                   [G1 e]
// kk12-15 W2                                   [G2]
// kk16-23 Wg (e, de)                           [G3]
// kk24-31 Wm (hs rows 0-63, e_new rows 128-191)[G4]
#define KK_SM 32
#define NFRAG 8
__device__ uint4 g_Wf[KK_SM * NFRAG * 32];
__device__ uint4 g_Wc[4 * NFRAG * 32];
__device__ uint4 g_W1f[NNODE * 4 * NFRAG * 32];
__device__ float d_b1p[NNODE * DD];
__device__ float d_bmp[NNODE * DD];
__device__ float d_agg[NNODE * DD];

#define SWF_U4   (KK_SM * NFRAG * 32)               // 8192 uint4 = 32768 u32
#define OFF_B1P  (SWF_U4 * 4)                       // 32768
#define OFF_B2   (OFF_B1P + 64)
#define OFF_BG   (OFF_B2 + 64)
#define OFF_BMP  (OFF_BG + 64)
#define OFF_SHI  (OFF_BMP + 64)
#define OFF_RED  (OFF_SHI + 64)
#define OFF_EPF  (OFF_RED + 512)                    // float2-aligned
#define EPF_WORDS (2 * 16 * NTH * 2)
#define SMEM_U32 (OFF_EPF + EPF_WORDS)
#define SMEM_BYTES (SMEM_U32 * 4)

// sigmoid via hardware tanh: 1 MUFU + 1 FMA
__device__ __forceinline__ float fsig(float x) {
    float th;
    asm("tanh.approx.f32 %0, %1;" : "=f"(th) : "f"(0.5f * x));
    return fmaf(0.5f, th, 0.5f);
}
// silu(x) = 0.5x + 0.5x*tanh(x/2) : mul + MUFU + fma
__device__ __forceinline__ float fsilu(float x) {
    float hx = 0.5f * x;
    float th;
    asm("tanh.approx.f32 %0, %1;" : "=f"(th) : "f"(hx));
    return fmaf(hx, th, hx);
}

__device__ __forceinline__ uint32_t smem_u32(const void *p) {
    uint32_t a;
    asm("{ .reg .u64 t; cvta.to.shared.u64 t, %1; cvt.u32.u64 %0, t; }" : "=r"(a) : "l"(p));
    return a;
}

// fast split: hi = bf16x2(v1,v0) via single packed cvt; lo = bf16x2(residuals)
__device__ __forceinline__ void splitpk(float v0, float v1, unsigned &whi, unsigned &wlo) {
    unsigned ph;
    asm("cvt.rn.bf16x2.f32 %0, %1, %2;" : "=r"(ph) : "f"(v1), "f"(v0));
    float f0 = __uint_as_float(ph << 16);
    float f1 = __uint_as_float(ph & 0xffff0000u);
    asm("cvt.rn.bf16x2.f32 %0, %1, %2;" : "=r"(wlo) : "f"(v1 - f1), "f"(v0 - f0));
    whi = ph;
}
// hi-only pack (for terms where the A-residual is dropped)
__device__ __forceinline__ unsigned pk2(float v0, float v1) {
    unsigned ph;
    asm("cvt.rn.bf16x2.f32 %0, %1, %2;" : "=r"(ph) : "f"(v1), "f"(v0));
    return ph;
}
__device__ __forceinline__ void up2(unsigned w, float &f0, float &f1) {
    f0 = __uint_as_float(w << 16);
    f1 = __uint_as_float(w & 0xffff0000u);
}
// reconstruct float2 from hi+lo frag words
__device__ __forceinline__ float2 rec2(unsigned wh, unsigned wl) {
    float h0, h1, l0, l1;
    up2(wh, h0, h1);
    up2(wl, l0, l1);
    return make_float2(h0 + l0, h1 + l1);
}

__device__ __forceinline__ void mma4(float *d, const unsigned *a, unsigned b0, unsigned b1) {
    asm("mma.sync.aligned.m16n8k16.row.col.f32.bf16.bf16.f32 "
        "{%0,%1,%2,%3}, {%4,%5,%6,%7}, {%8,%9}, {%0,%1,%2,%3};"
        : "+f"(d[0]), "+f"(d[1]), "+f"(d[2]), "+f"(d[3])
        : "r"(a[0]), "r"(a[1]), "r"(a[2]), "r"(a[3]), "r"(b0), "r"(b1));
}

// 3-term k16-step (full precision): ah*bh, ah*bl, al*bh
__device__ __forceinline__ void gemm_kk(float (&D)[8][4], const unsigned *ah, const unsigned *al,
                                        const uint4 *__restrict__ Wp)
{
#pragma unroll
    for (int grp = 0; grp < 2; grp++) {
        uint4 bq[4];
#pragma unroll
        for (int q = 0; q < 4; q++) bq[q] = Wp[(grp * 4 + q) * 32];
#pragma unroll
        for (int q = 0; q < 4; q++) mma4(D[grp * 4 + q], ah, bq[q].x, bq[q].y);
#pragma unroll
        for (int q = 0; q < 4; q++) mma4(D[grp * 4 + q], ah, bq[q].z, bq[q].w);
#pragma unroll
        for (int q = 0; q < 4; q++) mma4(D[grp * 4 + q], al, bq[q].x, bq[q].y);
    }
}

// 2-term k16-step (A-residual dropped; W keeps hi+lo -> no systematic W error)
__device__ __forceinline__ void gemm_kk2(float (&D)[8][4], const unsigned *ah,
                                         const uint4 *__restrict__ Wp)
{
#pragma unroll
    for (int grp = 0; grp < 2; grp++) {
        uint4 bq[4];
#pragma unroll
        for (int q = 0; q < 4; q++) bq[q] = Wp[(grp * 4 + q) * 32];
#pragma unroll
        for (int q = 0; q < 4; q++) mma4(D[grp * 4 + q], ah, bq[q].x, bq[q].y);
#pragma unroll
        for (int q = 0; q < 4; q++) mma4(D[grp * 4 + q], ah, bq[q].z, bq[q].w);
    }
}

__device__ __forceinline__ void cp_async8(uint32_t saddr, const void *gaddr) {
    asm volatile("cp.async.ca.shared.global [%0], [%1], 8;" :: "r"(saddr), "l"(gaddr) : "memory");
}

// ---- prep: pack weight B-fragments (hi/lo bf16) ----
__global__ void prep_kernel(const float *__restrict__ W1, const float *__restrict__ W2,
                            const float *__restrict__ Wg, const float *__restrict__ Wm)
{
    const int kk = blockIdx.x;          // 0..35 (32-35 = W1c -> g_Wc)
    const int tid = threadIdx.x;
    const int f = tid >> 5;
    const int lane = tid & 31;
    const int t = lane & 3;
    const int n = 8 * f + (lane >> 2);

    const float *W; int kb;
    if (kk < 8)       { W = W1; kb = kk * 16; }
    else if (kk < 12) { W = W1; kb = 192 + (kk - 8) * 16; }
    else if (kk < 16) { W = W2; kb = (kk - 12) * 16; }
    else if (kk < 24) { W = Wg; kb = (kk - 16) * 16; }
    else if (kk < 28) { W = Wm; kb = (kk - 24) * 16; }
    else if (kk < 32) { W = Wm; kb = 128 + (kk - 28) * 16; }
    else              { W = W1; kb = 128 + (kk - 32) * 16; }

    float w0 = W[(kb + 2 * t) * 64 + n];
    float w1 = W[(kb + 2 * t + 1) * 64 + n];
    float w2 = W[(kb + 2 * t + 8) * 64 + n];
    float w3 = W[(kb + 2 * t + 9) * 64 + n];
    unsigned h0, l0, h1, l1;
    splitpk(w0, w1, h0, l0);
    splitpk(w2, w3, h1, l1);
    if (kk < 32) g_Wf[(kk * NFRAG + f) * 32 + lane] = make_uint4(h0, h1, l0, l1);
    else         g_Wc[((kk - 32) * NFRAG + f) * 32 + lane] = make_uint4(h0, h1, l0, l1);
}

// ---- fold W1a' = W1a + diag(ht)*W1c per node ----
__global__ void fold_w1a_kernel(const float *__restrict__ h)
{
    const int gid = blockIdx.x * 256 + threadIdx.x;
    const int node = gid >> 10;
    const int idx = gid & 1023;
    const int kk_ = idx >> 8;
    const int t_ = idx & 3;
    const int kl = kk_ * 16 + 2 * t_;
    const float *hp = &h[node * DD];

    uint4 va = g_Wf[idx];
    uint4 vc = g_Wc[idx];
    float a0, a1, a2, a3, x0, x1, x2, x3;
    float c0, c1, c2, c3, y0, y1, y2, y3;
    up2(va.x, a0, a1); up2(va.z, x0, x1); a0 += x0; a1 += x1;
    up2(va.y, a2, a3); up2(va.w, x2, x3); a2 += x2; a3 += x3;
    up2(vc.x, c0, c1); up2(vc.z, y0, y1); c0 += y0; c1 += y1;
    up2(vc.y, c2, c3); up2(vc.w, y2, y3); c2 += y2; c3 += y3;
    unsigned nh0, nl0, nh1, nl1;
    splitpk(fmaf(hp[kl], c0, a0), fmaf(hp[kl + 1], c1, a1), nh0, nl0);
    splitpk(fmaf(hp[kl + 8], c2, a2), fmaf(hp[kl + 9], c3, a3), nh1, nl1);
    g_W1f[node * 1024 + idx] = make_uint4(nh0, nh1, nl0, nl1);
}

// ---- fold biases per node ----
__global__ void fold_bias_kernel(const float *__restrict__ h,
                                 const float *__restrict__ W1, const float *__restrict__ b1,
                                 const float *__restrict__ Wm, const float *__restrict__ bm)
{
    __shared__ float sh[64];
    const int node = blockIdx.x;
    const int c = threadIdx.x;
    sh[c] = h[node * DD + c];
    __syncthreads();
    float a = b1[c], m = bm[c];
#pragma unroll 8
    for (int k = 0; k < 64; k++) {
        a = fmaf(sh[k], W1[k * 64 + c], a);
        m = fmaf(sh[k], Wm[(64 + k) * 64 + c], m);
    }
    d_b1p[node * DD + c] = a;
    d_bmp[node * DD + c] = m;
}

__global__ void __launch_bounds__(NTH, 1) edge_kernel(
    const float *__restrict__ h, const float *__restrict__ e,
    const float *__restrict__ b2, const float *__restrict__ bg,
    float *__restrict__ e_out)
{
    extern __shared__ unsigned smu[];
    uint4 *sWfm = (uint4 *)smu;
    const uint4 *sW4 = (const uint4 *)smu;
    float *sb1p = (float *)(smu + OFF_B1P);
    float *sb2 = (float *)(smu + OFF_B2);
    float *sbg = (float *)(smu + OFF_BG);
    float *sbmp = (float *)(smu + OFF_BMP);
    float *shi = (float *)(smu + OFF_SHI);
    float *sred = (float *)(smu + OFF_RED);

    const int tid = threadIdx.x;
    const int w = tid >> 5;
    const int lane = tid & 31;
    const int g = lane >> 2;
    const int t = lane & 3;

    const int blk = blockIdx.x;
    const int b = blk / NN;
    const int i = blk - b * NN;
    const size_t erow = ((size_t)(b * NN + i)) * NN;
    const int node = b * NN + i;

    const uint32_t epfBase = smem_u32(smu + OFF_EPF);
    const float2 *epfRd = (const float2 *)(smu + OFF_EPF);

    // ---- stage weights (kk0-3 per-node) + biases + h_i ----
    {
        const uint4 *wsrc = &g_W1f[node * 1024];
        for (int idx = tid; idx < SWF_U4; idx += NTH)
            sWfm[idx] = (idx < 1024) ? wsrc[idx] : g_Wf[idx];
    }
    if (tid < 64) {
        sb1p[tid] = d_b1p[node * DD + tid];
        sbmp[tid] = d_bmp[node * DD + tid];
        sb2[tid] = b2[tid];
        sbg[tid] = bg[tid];
        shi[tid] = h[node * DD + tid];
    }
    __syncthreads();

    float2 aggc[8];
#pragma unroll
    for (int f = 0; f < 8; f++) aggc[f] = make_float2(0.f, 0.f);

    for (int j0 = 0; j0 < NN; j0 += 128) {
        const int rA = j0 + 16 * w + g;
        const int rB = rA + 8;
        const float *hA = &h[(b * NN + rA) * DD];
        const float *hB = &h[(b * NN + rB) * DD];

        // ---- prefetch next tile's e (per-thread slots; no barrier needed) ----
        const int nb = (j0 >> 7) & 1;
        const bool havePf = (j0 + 128 < NN);
        if (havePf) {
            const float *enA = &e[(erow + rA + 128) * DD];
            const float *enB = &e[(erow + rB + 128) * DD];
#pragma unroll
            for (int m = 0; m < 4; m++)
#pragma unroll
                for (int p = 0; p < 2; p++) {
                    const int c = 16 * m + 8 * p + 2 * t;
                    const int q = m * 4 + p * 2;
                    cp_async8(epfBase + nb * (16 * NTH * 8) + q * (NTH * 8) + tid * 8, &enA[c]);
                    cp_async8(epfBase + nb * (16 * NTH * 8) + (q + 1) * (NTH * 8) + tid * 8, &enB[c]);
                }
            asm volatile("cp.async.commit_group;" ::: "memory");
        }

        // ---- load hs + e; split ONCE into canonical frags ----
        unsigned hsFh[4][4], hsFl[4][4], eFh[4][4], eFl[4][4];
#pragma unroll
        for (int m = 0; m < 4; m++)
#pragma unroll
            for (int p = 0; p < 2; p++) {
                const int c = 16 * m + 8 * p + 2 * t;
                float2 a = *(const float2 *)&hA[c];
                float2 bv = *(const float2 *)&hB[c];
                splitpk(a.x, a.y, hsFh[m][2 * p], hsFl[m][2 * p]);
                splitpk(bv.x, bv.y, hsFh[m][2 * p + 1], hsFl[m][2 * p + 1]);
            }
        if (j0 == 0) {
            const float *epA = &e[(erow + rA) * DD];
            const float *epB = &e[(erow + rB) * DD];
#pragma unroll
            for (int m = 0; m < 4; m++)
#pragma unroll
                for (int p = 0; p < 2; p++) {
                    const int c = 16 * m + 8 * p + 2 * t;
                    float2 ev = *(const float2 *)&epA[c];
                    float2 ew = *(const float2 *)&epB[c];
                    splitpk(ev.x, ev.y, eFh[m][2 * p], eFl[m][2 * p]);
                    splitpk(ew.x, ew.y, eFh[m][2 * p + 1], eFl[m][2 * p + 1]);
                }
        } else {
            if (havePf) asm volatile("cp.async.wait_group 1;" ::: "memory");
            else        asm volatile("cp.async.wait_group 0;" ::: "memory");
            const int pb = ((j0 >> 7) + 1) & 1;   // buffer written last tile
            const float2 *pf = epfRd + pb * (16 * NTH) + tid;
#pragma unroll
            for (int m = 0; m < 4; m++)
#pragma unroll
                for (int p = 0; p < 2; p++) {
                    const int q = m * 4 + p * 2;
                    float2 ev = pf[q * NTH];
                    float2 ew = pf[(q + 1) * NTH];
                    splitpk(ev.x, ev.y, eFh[m][2 * p], eFl[m][2 * p]);
                    splitpk(ew.x, ew.y, eFh[m][2 * p + 1], eFl[m][2 * p + 1]);
                }
        }

        // ---- G1: D = hs@W1a' + |hs-ht|@W1b + e@W1d  (3-term, output-critical) ----
        float D[8][4];
#pragma unroll
        for (int f = 0; f < 8; f++) { D[f][0] = D[f][1] = D[f][2] = D[f][3] = 0.f; }
#pragma unroll
        for (int m = 0; m < 4; m++)
            gemm_kk(D, hsFh[m], hsFl[m], sW4 + (m * 8) * 32 + lane);
#pragma unroll
        for (int m = 0; m < 4; m++) {
            // |hs - ht| rebuilt from frags; ht from smem
            unsigned dh_[4], dl_[4];
#pragma unroll
            for (int p = 0; p < 2; p++) {
                const int c = 16 * m + 8 * p + 2 * t;
                float2 ht2 = *(const float2 *)&shi[c];
                float2 va = rec2(hsFh[m][2 * p], hsFl[m][2 * p]);
                float2 vb = rec2(hsFh[m][2 * p + 1], hsFl[m][2 * p + 1]);
                splitpk(fabsf(va.x - ht2.x), fabsf(va.y - ht2.y), dh_[2 * p], dl_[2 * p]);
                splitpk(fabsf(vb.x - ht2.x), fabsf(vb.y - ht2.y), dh_[2 * p + 1], dl_[2 * p + 1]);
            }
            gemm_kk(D, dh_, dl_, sW4 + ((4 + m) * 8) * 32 + lane);
        }
#pragma unroll
        for (int m = 0; m < 4; m++)
            gemm_kk(D, eFh[m], eFl[m], sW4 + ((8 + m) * 8) * 32 + lane);

        // ---- t1 = silu(D + b1') as A-frags ----
        unsigned t1h[4][4], t1l[4][4];
#pragma unroll
        for (int m = 0; m < 4; m++) {
            const int f0 = 2 * m, f1 = 2 * m + 1;
            float2 bb0 = *(const float2 *)&sb1p[8 * f0 + 2 * t];
            float2 bb1 = *(const float2 *)&sb1p[8 * f1 + 2 * t];
            splitpk(fsilu(D[f0][0] + bb0.x), fsilu(D[f0][1] + bb0.y), t1h[m][0], t1l[m][0]);
            splitpk(fsilu(D[f0][2] + bb0.x), fsilu(D[f0][3] + bb0.y), t1h[m][1], t1l[m][1]);
            splitpk(fsilu(D[f1][0] + bb1.x), fsilu(D[f1][1] + bb1.y), t1h[m][2], t1l[m][2]);
            splitpk(fsilu(D[f1][2] + bb1.x), fsilu(D[f1][3] + bb1.y), t1h[m][3], t1l[m][3]);
        }

        // ---- G2: D2 = t1 @ W2 (+b2 in place)  (3-term, de is output-critical) ----
        float D2[8][4];
#pragma unroll
        for (int f = 0; f < 8; f++) { D2[f][0] = D2[f][1] = D2[f][2] = D2[f][3] = 0.f; }
#pragma unroll
        for (int kk = 0; kk < 4; kk++)
            gemm_kk(D2, t1h[kk], t1l[kk], sW4 + ((12 + kk) * 8) * 32 + lane);
#pragma unroll
        for (int f = 0; f < 8; f++) {
            float2 bb = *(const float2 *)&sb2[8 * f + 2 * t];
            D2[f][0] += bb.x; D2[f][1] += bb.y; D2[f][2] += bb.x; D2[f][3] += bb.y;
        }

        // ---- G3: D3 = [e, de] @ Wg  (2-term: gate error damped by g(1-g)) ----
        float D3[8][4];
#pragma unroll
        for (int f = 0; f < 8; f++) { D3[f][0] = D3[f][1] = D3[f][2] = D3[f][3] = 0.f; }
#pragma unroll
        for (int kk = 0; kk < 4; kk++)
            gemm_kk2(D3, eFh[kk], sW4 + ((16 + kk) * 8) * 32 + lane);
#pragma unroll
        for (int kk = 0; kk < 4; kk++) {     // de block: hi-only pack
            unsigned ah[4];
            ah[0] = pk2(D2[2 * kk][0], D2[2 * kk][1]);
            ah[1] = pk2(D2[2 * kk][2], D2[2 * kk][3]);
            ah[2] = pk2(D2[2 * kk + 1][0], D2[2 * kk + 1][1]);
            ah[3] = pk2(D2[2 * kk + 1][2], D2[2 * kk + 1][3]);
            gemm_kk2(D3, ah, sW4 + ((20 + kk) * 8) * 32 + lane);
        }

        // ---- e_new = de + g*(e - de); store; refill eFh with e_new (hi only) ----
        float *eoA = &e_out[(erow + rA) * DD];
        float *eoB = &e_out[(erow + rB) * DD];
#pragma unroll
        for (int m = 0; m < 4; m++)
#pragma unroll
            for (int p = 0; p < 2; p++) {
                const int f = 2 * m + p;
                float2 bb = *(const float2 *)&sbg[8 * f + 2 * t];
                float2 ea = rec2(eFh[m][2 * p], eFl[m][2 * p]);
                float2 eb = rec2(eFh[m][2 * p + 1], eFl[m][2 * p + 1]);
                float g0 = fsig(D3[f][0] + bb.x), g1 = fsig(D3[f][1] + bb.y);
                float g2 = fsig(D3[f][2] + bb.x), g3 = fsig(D3[f][3] + bb.y);
                float2 nA, nB;
                nA.x = fmaf(g0, ea.x - D2[f][0], D2[f][0]);
                nA.y = fmaf(g1, ea.y - D2[f][1], D2[f][1]);
                nB.x = fmaf(g2, eb.x - D2[f][2], D2[f][2]);
                nB.y = fmaf(g3, eb.y - D2[f][3], D2[f][3]);
                const int c = 16 * m + 8 * p + 2 * t;
                *(float2 *)&eoA[c] = nA;
                *(float2 *)&eoB[c] = nB;
                eFh[m][2 * p] = pk2(nA.x, nA.y);
                eFh[m][2 * p + 1] = pk2(nB.x, nB.y);
            }

        // ---- G4: D4 = [hs, e_new] @ Wm'  (2-term: msg error averages over j in agg) ----
        float D4[8][4];
#pragma unroll
        for (int f = 0; f < 8; f++) { D4[f][0] = D4[f][1] = D4[f][2] = D4[f][3] = 0.f; }
#pragma unroll
        for (int kk = 0; kk < 4; kk++)
            gemm_kk2(D4, hsFh[kk], sW4 + ((24 + kk) * 8) * 32 + lane);
#pragma unroll
        for (int kk = 0; kk < 4; kk++)
            gemm_kk2(D4, eFh[kk], sW4 + ((28 + kk) * 8) * 32 + lane);

        // ---- msg = silu(D4 + bm'), diagonal mask, column-accumulate ----
        const bool mA = (rA != i), mB = (rB != i);
#pragma unroll
        for (int f = 0; f < 8; f++) {
            float2 bb = *(const float2 *)&sbmp[8 * f + 2 * t];
            float m0 = fsilu(D4[f][0] + bb.x), m1 = fsilu(D4[f][1] + bb.y);
            float m2 = fsilu(D4[f][2] + bb.x), m3 = fsilu(D4[f][3] + bb.y);
            aggc[f].x += (mA ? m0 : 0.f) + (mB ? m2 : 0.f);
            aggc[f].y += (mA ? m1 : 0.f) + (mB ? m3 : 0.f);
        }
    }

    // ---- agg reduce: over g lanes (shfl), then over warps (smem) ----
#pragma unroll
    for (int f = 0; f < 8; f++) {
        float x = aggc[f].x, y = aggc[f].y;
        x += __shfl_xor_sync(0xffffffffu, x, 4);
        x += __shfl_xor_sync(0xffffffffu, x, 8);
        x += __shfl_xor_sync(0xffffffffu, x, 16);
        y += __shfl_xor_sync(0xffffffffu, y, 4);
        y += __shfl_xor_sync(0xffffffffu, y, 8);
        y += __shfl_xor_sync(0xffffffffu, y, 16);
        aggc[f].x = x; aggc[f].y = y;
    }
    if (lane < 4) {
#pragma unroll
        for (int f = 0; f < 8; f++) {
            sred[w * 64 + 8 * f + 2 * lane] = aggc[f].x;
            sred[w * 64 + 8 * f + 2 * lane + 1] = aggc[f].y;
        }
    }
    __syncthreads();
    if (tid < 64) {
        float s = 0.f;
#pragma unroll
        for (int ww = 0; ww < 8; ww++) s += sred[ww * 64 + tid];
        d_agg[node * DD + tid] = s * (1.0f / (NN - 1));
    }
}

__global__ void __launch_bounds__(64) node_kernel(
    const float *__restrict__ h,
    const float *__restrict__ Wu, const float *__restrict__ bu,
    const float *__restrict__ Wg, const float *__restrict__ bg,
    float *__restrict__ h_out)
{
    __shared__ float xs[128];
    __shared__ float dhs[64];
    const int node = blockIdx.x;
    const int c = threadIdx.x;

    xs[c] = h[node * 64 + c];
    xs[64 + c] = d_agg[node * 64 + c];
    __syncthreads();

    float acc = bu[c];
#pragma unroll 8
    for (int k = 0; k < 128; k++) acc = fmaf(xs[k], Wu[k * 64 + c], acc);
    float dh = fsilu(acc);
    dhs[c] = dh;
    __syncthreads();

    float a2 = bg[c];
#pragma unroll 8
    for (int k = 0; k < 64; k++) a2 = fmaf(xs[k], Wg[k * 64 + c], a2);
#pragma unroll 8
    for (int k = 0; k < 64; k++) a2 = fmaf(dhs[k], Wg[(64 + k) * 64 + c], a2);
    float gg = fsig(a2);
    h_out[node * 64 + c] = gg * xs[c] + (1.0f - gg) * dh;
}

extern "C" void kernel_launch(void* const* d_in, const int* in_sizes, int n_in,
                              void* d_out, int out_size)
{
    const float* h   = (const float*)d_in[0];
    const float* e   = (const float*)d_in[1];
    const float* W1  = (const float*)d_in[2];
    const float* b1  = (const float*)d_in[3];
    const float* W2  = (const float*)d_in[4];
    const float* b2  = (const float*)d_in[5];
    const float* Weg = (const float*)d_in[6];
    const float* beg = (const float*)d_in[7];
    const float* Wm  = (const float*)d_in[8];
    const float* bm  = (const float*)d_in[9];
    const float* Wu  = (const float*)d_in[10];
    const float* bu  = (const float*)d_in[11];
    const float* Wga = (const float*)d_in[12];
    const float* bga = (const float*)d_in[13];

    float* out = (float*)d_out;
    float* h_out = out;                       // (B,N,D)
    float* e_out = out + BB * NN * DD;        // (B,N,N,D)

    cudaFuncSetAttribute(edge_kernel, cudaFuncAttributeMaxDynamicSharedMemorySize, SMEM_BYTES);

    prep_kernel<<<36, 256>>>(W1, W2, Weg, Wm);
    fold_w1a_kernel<<<NNODE * 1024 / 256, 256>>>(h);
    fold_bias_kernel<<<NNODE, 64>>>(h, W1, b1, Wm, bm);
    edge_kernel<<<NNODE, NTH, SMEM_BYTES>>>(h, e, b2, beg, e_out);
    node_kernel<<<NNODE, 64>>>(h, Wu, bu, Wga, bga, h_out);
}